// round 5
// baseline (speedup 1.0000x reference)
#include <cuda_runtime.h>
#include <cstdint>

#define AN 13824          // 24*24*24 anchors
#define NT 512            // threads per block (kernel 1)
#define NV 3456           // AN/4 float4s
#define PERV 7            // ceil(NV/NT): 6 full + 1 partial (t<384)
#define NK 28             // keys per thread (4*PERV), tail zero-padded
#define TK 60             // TOPK
#define NMSK 20           // NMS_TOPK
#define CAP 1024          // candidate capacity
#define NB 256            // batches
#define T1 0xC0100000u    // fkey(2.25f)

__device__ int   g_idx[NB * TK];
__device__ float g_sc[NB * TK];

__device__ __forceinline__ unsigned int fkey(float x) {
    unsigned int b = __float_as_uint(x);
    return (b & 0x80000000u) ? ~b : (b | 0x80000000u);
}
__device__ __forceinline__ float fkey_inv(unsigned int u) {
    unsigned int b = (u & 0x80000000u) ? (u & 0x7fffffffu) : ~u;
    return __uint_as_float(b);
}

// ---------------- Kernel 1: top-60 selection ----------------
__global__ __launch_bounds__(NT, 2)
void select_topk_kernel(const float* __restrict__ cls)
{
    const int b    = blockIdx.x;
    const int t    = threadIdx.x;
    const int lane = t & 31;
    const int wid  = t >> 5;

    __shared__ int s_wcnt[2][16];
    __shared__ unsigned long long s_cand[CAP];
    __shared__ int s_ncand;

    // Phase 1: vectorized load + fkey
    const float4* cb4 = (const float4*)(cls + (size_t)b * AN);
    unsigned int keys[NK];
#pragma unroll
    for (int j = 0; j < 6; j++) {
        float4 v = __ldg(&cb4[t + NT * j]);
        keys[4 * j + 0] = fkey(v.x);
        keys[4 * j + 1] = fkey(v.y);
        keys[4 * j + 2] = fkey(v.z);
        keys[4 * j + 3] = fkey(v.w);
    }
    if (t < NV - NT * 6) {           // t < 384
        float4 v = __ldg(&cb4[t + NT * 6]);
        keys[24] = fkey(v.x); keys[25] = fkey(v.y);
        keys[26] = fkey(v.z); keys[27] = fkey(v.w);
    } else {
        keys[24] = keys[25] = keys[26] = keys[27] = 0u;
    }

    if (t == 0) s_ncand = 0;

    // Phase 2: one-pass count at fixed threshold T1
    int c = 0;
#pragma unroll
    for (int j = 0; j < NK; j++)
        c += (keys[j] >= T1);
    unsigned int wsum = __reduce_add_sync(0xffffffffu, (unsigned int)c);
    if (lane == 0) s_wcnt[0][wid] = (int)wsum;
    __syncthreads();
    int tot = 0;
#pragma unroll
    for (int w = 0; w < 16; w++)
        tot += s_wcnt[0][w];

    unsigned int cut;
    if (tot >= TK && tot <= CAP) {
        cut = T1;                    // fast path (always taken for N(0,1) data)
    } else {
        // Fallback: binary search for largest 11-bit prefix T with count >= TK
        unsigned int T = 0;
#pragma unroll
        for (int bit = 10; bit >= 0; bit--) {
            unsigned int candT = T | (1u << bit);
            unsigned int Tsh = candT << 21;
            int cc = 0;
#pragma unroll
            for (int j = 0; j < NK; j++)
                cc += (keys[j] >= Tsh);
            unsigned int ws = __reduce_add_sync(0xffffffffu, (unsigned int)cc);
            int buf = bit & 1;
            if (lane == 0) s_wcnt[buf][wid] = (int)ws;
            __syncthreads();
            int tt = 0;
#pragma unroll
            for (int w = 0; w < 16; w++)
                tt += s_wcnt[buf][w];
            if (tt >= TK) T = candT;
            __syncthreads();
        }
        cut = T << 21;
        if (cut == 0) cut = 1;       // never collect zero-padded slots
    }

    // Phase 3: collect candidates (key >= cut)
#pragma unroll
    for (int j = 0; j < NK; j++) {
        if (keys[j] >= cut) {
            int idx = 4 * (t + NT * (j >> 2)) + (j & 3);
            if (idx < AN) {
                int pos = atomicAdd(&s_ncand, 1);
                if (pos < CAP)
                    s_cand[pos] = ((unsigned long long)keys[j] << 14) |
                                  (unsigned long long)(16383 - idx);
            }
        }
    }
    __syncthreads();

    // Phase 4: exact ranking; write top-60 (idx, score) to global scratch
    {
        int C = s_ncand;
        if (C > CAP) C = CAP;
        for (int cc = t; cc < C; cc += NT) {
            unsigned long long k = s_cand[cc];
            int r = 0;
#pragma unroll 4
            for (int m = 0; m < C; m++)
                r += (s_cand[m] > k);
            if (r < TK) {
                int idx = 16383 - (int)(k & 16383ull);
                float logit = fkey_inv((unsigned int)(k >> 14));
                g_idx[b * TK + r] = idx;
                g_sc[b * TK + r]  = 1.0f / (1.0f + expf(-logit));
            }
        }
    }
}

// ---------------- Kernel 2: gather + IoU + NMS + write ----------------
__global__ __launch_bounds__(128, 8)
void nms_kernel(const float* __restrict__ shp,
                const float* __restrict__ off,
                float* __restrict__ out)
{
    const int b    = blockIdx.x;
    const int t    = threadIdx.x;
    const int lane = t & 31;
    const int wid  = t >> 5;

    __shared__ float s_sc[TK];
    __shared__ float s_ctr[TK][3];
    __shared__ float s_sz[TK][3];
    __shared__ float s_lo[TK][3];
    __shared__ float s_hi[TK][3];
    __shared__ float s_vol[TK];
    __shared__ float s_iou[TK * TK];
    __shared__ int   s_candf[TK], s_kept[TK], s_supp[TK];
    __shared__ int   s_src[TK];
    __shared__ int   s_nk;

    // gather boxes
    if (t < TK) {
        int idx = g_idx[b * TK + t];
        s_sc[t] = g_sc[b * TK + t];
        int z   = idx / 576;
        int rem = idx - z * 576;
        int y   = rem / 24;
        int x   = rem - y * 24;
        size_t base = (size_t)b * 3 * AN;
        float oz = __ldg(&off[base + 0 * AN + idx]);
        float oy = __ldg(&off[base + 1 * AN + idx]);
        float ox = __ldg(&off[base + 2 * AN + idx]);
        float s0 = __ldg(&shp[base + 0 * AN + idx]);
        float s1 = __ldg(&shp[base + 1 * AN + idx]);
        float s2 = __ldg(&shp[base + 2 * AN + idx]);
        float cz = ((float)z + oz) * 4.0f;   // stride = 96/24 = 4
        float cy = ((float)y + oy) * 4.0f;
        float cx = ((float)x + ox) * 4.0f;
        float dz = 2.0f * s0, dy = 2.0f * s1, dx = 2.0f * s2;
        s_ctr[t][0] = cz; s_ctr[t][1] = cy; s_ctr[t][2] = cx;
        s_sz[t][0]  = dz; s_sz[t][1]  = dy; s_sz[t][2]  = dx;
        s_lo[t][0] = cz - dz * 0.5f; s_lo[t][1] = cy - dy * 0.5f; s_lo[t][2] = cx - dx * 0.5f;
        s_hi[t][0] = cz + dz * 0.5f; s_hi[t][1] = cy + dy * 0.5f; s_hi[t][2] = cx + dx * 0.5f;
        s_vol[t] = dz * dy * dx;
        s_supp[t] = 0;
        s_kept[t] = 0;
    }
    __syncthreads();

    // IoU matrix
    if (t < TK) {
        float l0 = s_lo[t][0], l1 = s_lo[t][1], l2 = s_lo[t][2];
        float h0 = s_hi[t][0], h1 = s_hi[t][1], h2 = s_hi[t][2];
        float vi = s_vol[t];
        for (int j = 0; j < TK; j++) {
            float iz = fminf(h0, s_hi[j][0]) - fmaxf(l0, s_lo[j][0]);
            float iy = fminf(h1, s_hi[j][1]) - fmaxf(l1, s_lo[j][1]);
            float ix = fminf(h2, s_hi[j][2]) - fmaxf(l2, s_lo[j][2]);
            float inter = fmaxf(iz, 0.0f) * fmaxf(iy, 0.0f) * fmaxf(ix, 0.0f);
            float uni = vi + s_vol[j] - inter;
            s_iou[t * TK + j] = inter / fmaxf(uni, 1e-8f);
        }
    }
    __syncthreads();

    // sequential NMS on warp 0
    if (wid == 0) {
        if (lane == 0) {
            int r = 0;
            for (int i = 0; i < TK; i++) {
                int v = s_sc[i] > 0.15f;
                s_candf[i] = v && (r < NMSK);
                r += v;
            }
        }
        __syncwarp();
        for (int i = 0; i < TK; i++) {
            int keep = s_candf[i] && !s_supp[i];
            if (lane == 0) s_kept[i] = keep;
            if (keep) {
                for (int m = lane; m < TK; m += 32)
                    if (m != i && s_iou[i * TK + m] > 0.05f) s_supp[m] = 1;
            }
            __syncwarp();
        }
        if (lane == 0) {
            int nk = 0;
            for (int i = 0; i < TK; i++)
                if (s_kept[i]) s_src[nk++] = i;
            s_nk = nk;
        }
    }
    __syncthreads();

    // write output (kept-first, -1 padding)
    float* ob = out + (size_t)b * TK * 8;
    if (t < TK) {
        if (t < s_nk) {
            int i = s_src[t];
            ob[t * 8 + 0] = 1.0f;
            ob[t * 8 + 1] = s_sc[i];
            ob[t * 8 + 2] = s_ctr[i][0];
            ob[t * 8 + 3] = s_ctr[i][1];
            ob[t * 8 + 4] = s_ctr[i][2];
            ob[t * 8 + 5] = s_sz[i][0];
            ob[t * 8 + 6] = s_sz[i][1];
            ob[t * 8 + 7] = s_sz[i][2];
        } else {
#pragma unroll
            for (int cch = 0; cch < 8; cch++)
                ob[t * 8 + cch] = -1.0f;
        }
    }
}

extern "C" void kernel_launch(void* const* d_in, const int* in_sizes, int n_in,
                              void* d_out, int out_size)
{
    const float* cls = (const float*)d_in[0];
    const float* shp = (const float*)d_in[1];
    const float* off = (const float*)d_in[2];
    float* out = (float*)d_out;
    select_topk_kernel<<<NB, NT>>>(cls);
    nms_kernel<<<NB, 128>>>(shp, off, out);
}

// round 6
// speedup vs baseline: 1.3190x; 1.3190x over previous
#include <cuda_runtime.h>
#include <cstdint>

#define AN 13824          // 24*24*24 anchors
#define NT 512            // threads per block (kernel 1)
#define NV 3456           // AN/4 float4s
#define NK 28             // keys per thread (4*7), tail zero-padded
#define TK 60             // TOPK
#define NMSK 20           // NMS_TOPK
#define CAP 1024          // candidate capacity
#define NB 256            // batches
#define T1 0xC0100000u    // fkey(2.25f)

__device__ int   g_idx[NB * TK];
__device__ float g_sc[NB * TK];

__device__ __forceinline__ unsigned int fkey(float x) {
    unsigned int b = __float_as_uint(x);
    return (b & 0x80000000u) ? ~b : (b | 0x80000000u);
}
__device__ __forceinline__ float fkey_inv(unsigned int u) {
    unsigned int b = (u & 0x80000000u) ? (u & 0x7fffffffu) : ~u;
    return __uint_as_float(b);
}

// ---------------- Kernel 1: top-60 selection ----------------
__global__ __launch_bounds__(NT, 2)
void select_topk_kernel(const float* __restrict__ cls)
{
    const int b    = blockIdx.x;
    const int t    = threadIdx.x;
    const int lane = t & 31;
    const int wid  = t >> 5;

    __shared__ int s_wcnt[2][16];
    __shared__ unsigned long long s_cand[CAP];
    __shared__ int s_ncand;

    const float4* cb4 = (const float4*)(cls + (size_t)b * AN);
    unsigned int keys[NK];
#pragma unroll
    for (int j = 0; j < 6; j++) {
        float4 v = __ldg(&cb4[t + NT * j]);
        keys[4 * j + 0] = fkey(v.x);
        keys[4 * j + 1] = fkey(v.y);
        keys[4 * j + 2] = fkey(v.z);
        keys[4 * j + 3] = fkey(v.w);
    }
    if (t < NV - NT * 6) {           // t < 384
        float4 v = __ldg(&cb4[t + NT * 6]);
        keys[24] = fkey(v.x); keys[25] = fkey(v.y);
        keys[26] = fkey(v.z); keys[27] = fkey(v.w);
    } else {
        keys[24] = keys[25] = keys[26] = keys[27] = 0u;
    }

    if (t == 0) s_ncand = 0;

    // one-pass count at fixed threshold T1
    int c = 0;
#pragma unroll
    for (int j = 0; j < NK; j++)
        c += (keys[j] >= T1);
    unsigned int wsum = __reduce_add_sync(0xffffffffu, (unsigned int)c);
    if (lane == 0) s_wcnt[0][wid] = (int)wsum;
    __syncthreads();
    int tot = 0;
#pragma unroll
    for (int w = 0; w < 16; w++)
        tot += s_wcnt[0][w];

    unsigned int cut;
    if (tot >= TK && tot <= CAP) {
        cut = T1;                    // fast path (always taken for N(0,1) data)
    } else {
        // fallback: binary search for largest 11-bit prefix with count >= TK
        unsigned int T = 0;
#pragma unroll
        for (int bit = 10; bit >= 0; bit--) {
            unsigned int candT = T | (1u << bit);
            unsigned int Tsh = candT << 21;
            int cc = 0;
#pragma unroll
            for (int j = 0; j < NK; j++)
                cc += (keys[j] >= Tsh);
            unsigned int ws = __reduce_add_sync(0xffffffffu, (unsigned int)cc);
            int buf = bit & 1;
            if (lane == 0) s_wcnt[buf][wid] = (int)ws;
            __syncthreads();
            int tt = 0;
#pragma unroll
            for (int w = 0; w < 16; w++)
                tt += s_wcnt[buf][w];
            if (tt >= TK) T = candT;
            __syncthreads();
        }
        cut = T << 21;
        if (cut == 0) cut = 1;       // never collect zero-padded slots
    }

    // collect candidates
#pragma unroll
    for (int j = 0; j < NK; j++) {
        if (keys[j] >= cut) {
            int idx = 4 * (t + NT * (j >> 2)) + (j & 3);
            if (idx < AN) {
                int pos = atomicAdd(&s_ncand, 1);
                if (pos < CAP)
                    s_cand[pos] = ((unsigned long long)keys[j] << 14) |
                                  (unsigned long long)(16383 - idx);
            }
        }
    }
    __syncthreads();

    // exact ranking; write top-60 (idx, score) to scratch
    {
        int C = s_ncand;
        if (C > CAP) C = CAP;
        for (int cc = t; cc < C; cc += NT) {
            unsigned long long k = s_cand[cc];
            int r = 0;
#pragma unroll 4
            for (int m = 0; m < C; m++)
                r += (s_cand[m] > k);
            if (r < TK) {
                int idx = 16383 - (int)(k & 16383ull);
                float logit = fkey_inv((unsigned int)(k >> 14));
                g_idx[b * TK + r] = idx;
                g_sc[b * TK + r]  = 1.0f / (1.0f + expf(-logit));
            }
        }
    }
}

// ---------------- Kernel 2: gather + bitmask IoU + bitmask NMS + write ----------------
__global__ __launch_bounds__(64, 16)
void nms_kernel(const float* __restrict__ shp,
                const float* __restrict__ off,
                float* __restrict__ out)
{
    const int b    = blockIdx.x;
    const int t    = threadIdx.x;
    const int lane = t & 31;
    const int wid  = t >> 5;

    __shared__ float s_l0[TK], s_l1[TK], s_l2[TK];
    __shared__ float s_h0[TK], s_h1[TK], s_h2[TK];
    __shared__ float s_vol[TK];
    __shared__ unsigned int s_mlo[TK], s_mhi[TK];
    __shared__ unsigned int s_valid[2];
    __shared__ unsigned long long s_kept;

    // --- gather + box build (registers) ---
    float sc = 0.0f, cz = 0, cy = 0, cx = 0, dz = 0, dy = 0, dx = 0;
    float l0 = 0, l1 = 0, l2 = 0, h0 = 0, h1 = 0, h2 = 0, vi = 0;
    if (t < TK) {
        int idx = g_idx[b * TK + t];
        sc = g_sc[b * TK + t];
        int z   = idx / 576;
        int rem = idx - z * 576;
        int y   = rem / 24;
        int x   = rem - y * 24;
        size_t base = (size_t)b * 3 * AN;
        float oz = __ldg(&off[base + 0 * AN + idx]);
        float oy = __ldg(&off[base + 1 * AN + idx]);
        float ox = __ldg(&off[base + 2 * AN + idx]);
        float s0 = __ldg(&shp[base + 0 * AN + idx]);
        float s1 = __ldg(&shp[base + 1 * AN + idx]);
        float s2 = __ldg(&shp[base + 2 * AN + idx]);
        cz = ((float)z + oz) * 4.0f;   // stride = 96/24 = 4
        cy = ((float)y + oy) * 4.0f;
        cx = ((float)x + ox) * 4.0f;
        dz = 2.0f * s0; dy = 2.0f * s1; dx = 2.0f * s2;
        l0 = cz - dz * 0.5f; l1 = cy - dy * 0.5f; l2 = cx - dx * 0.5f;
        h0 = cz + dz * 0.5f; h1 = cy + dy * 0.5f; h2 = cx + dx * 0.5f;
        vi = dz * dy * dx;
        s_l0[t] = l0; s_l1[t] = l1; s_l2[t] = l2;
        s_h0[t] = h0; s_h1[t] = h1; s_h2[t] = h2;
        s_vol[t] = vi;
    }
    // valid ballot (all 64 threads participate; rows 32..59 live in warp 1 lanes 0..27)
    unsigned int vb = __ballot_sync(0xffffffffu, (t < TK) && (sc > 0.15f));
    if (lane == 0) s_valid[wid] = vb;
    __syncthreads();

    // --- IoU threshold mask per row ---
    if (t < TK) {
        unsigned int mlo = 0, mhi = 0;
#pragma unroll 4
        for (int j = 0; j < TK; j++) {
            float iz = fminf(h0, s_h0[j]) - fmaxf(l0, s_l0[j]);
            float iy = fminf(h1, s_h1[j]) - fmaxf(l1, s_l1[j]);
            float ix = fminf(h2, s_h2[j]) - fmaxf(l2, s_l2[j]);
            float inter = fmaxf(iz, 0.0f) * fmaxf(iy, 0.0f) * fmaxf(ix, 0.0f);
            float uni = vi + s_vol[j] - inter;
            float iou = inter / fmaxf(uni, 1e-8f);
            unsigned int hit = (iou > 0.05f) && (j != t);
            if (j < 32) mlo |= hit << j;
            else        mhi |= hit << (j - 32);
        }
        s_mlo[t] = mlo;
        s_mhi[t] = mhi;
    }
    __syncthreads();

    // --- serial bitmask NMS on one thread (fully unrolled, register chain) ---
    if (t == 0) {
        unsigned long long valid = ((unsigned long long)s_valid[1] << 32) | s_valid[0];
        unsigned long long supp = 0, kept = 0;
        int r = 0;
#pragma unroll
        for (int i = 0; i < TK; i++) {
            unsigned long long mask_i =
                ((unsigned long long)s_mhi[i] << 32) | s_mlo[i];
            int v = (int)((valid >> i) & 1ull);
            int keep = v && (r < NMSK) && !((supp >> i) & 1ull);
            r += v;
            kept |= (unsigned long long)keep << i;
            if (keep) supp |= mask_i;
        }
        s_kept = kept;
    }
    __syncthreads();

    // --- output: kept rows (index order) first, -1 padding after ---
    float* ob = out + (size_t)b * TK * 8;
    if (t < TK) {
        unsigned long long kept = s_kept;
        int nk = __popcll(kept);
        if ((kept >> t) & 1ull) {
            int pos = __popcll(kept & ((1ull << t) - 1ull));
            float4* o4 = (float4*)(ob + pos * 8);
            o4[0] = make_float4(1.0f, sc, cz, cy);
            o4[1] = make_float4(cx, dz, dy, dx);
        }
        if (t >= nk) {
            float4* o4 = (float4*)(ob + t * 8);
            o4[0] = make_float4(-1.0f, -1.0f, -1.0f, -1.0f);
            o4[1] = make_float4(-1.0f, -1.0f, -1.0f, -1.0f);
        }
    }
}

extern "C" void kernel_launch(void* const* d_in, const int* in_sizes, int n_in,
                              void* d_out, int out_size)
{
    const float* cls = (const float*)d_in[0];
    const float* shp = (const float*)d_in[1];
    const float* off = (const float*)d_in[2];
    float* out = (float*)d_out;
    select_topk_kernel<<<NB, NT>>>(cls);
    nms_kernel<<<NB, 64>>>(shp, off, out);
}

// round 7
// speedup vs baseline: 1.4082x; 1.0676x over previous
#include <cuda_runtime.h>
#include <cstdint>

#define AN 13824          // 24*24*24 anchors
#define NT 512            // threads per block
#define NV 3456           // AN/4 float4s
#define NK 28             // keys per thread (4*7), tail zero-padded
#define TK 60             // TOPK
#define NMSK 20           // NMS_TOPK
#define CAP 1024          // candidate capacity
#define NB 256            // batches
#define T1 0xC0100000u    // fkey(2.25f)

__device__ __forceinline__ unsigned int fkey(float x) {
    unsigned int b = __float_as_uint(x);
    return (b & 0x80000000u) ? ~b : (b | 0x80000000u);
}
__device__ __forceinline__ float fkey_inv(unsigned int u) {
    unsigned int b = (u & 0x80000000u) ? (u & 0x7fffffffu) : ~u;
    return __uint_as_float(b);
}

__global__ __launch_bounds__(NT, 2)
void detect_fused_kernel(const float* __restrict__ cls,
                         const float* __restrict__ shp,
                         const float* __restrict__ off,
                         float* __restrict__ out)
{
    const int b    = blockIdx.x;
    const int t    = threadIdx.x;
    const int lane = t & 31;
    const int wid  = t >> 5;

    __shared__ int s_wcnt[2][16];
    __shared__ unsigned long long s_cand[CAP];
    __shared__ int   s_ncand;
    __shared__ int   s_idx[TK];
    __shared__ float s_sc[TK];
    __shared__ float s_gv[6][TK];          // gathered off(0..2)/shp(3..5) values
    __shared__ float s_l0[TK], s_l1[TK], s_l2[TK];
    __shared__ float s_h0[TK], s_h1[TK], s_h2[TK];
    __shared__ float s_vol[TK];
    __shared__ unsigned int s_mlo[TK], s_mhi[TK];
    __shared__ unsigned int s_valid[2];
    __shared__ unsigned long long s_kept;

    // ---------------- Phase 1: vectorized load + fkey ----------------
    const float4* cb4 = (const float4*)(cls + (size_t)b * AN);
    unsigned int keys[NK];
#pragma unroll
    for (int j = 0; j < 6; j++) {
        float4 v = __ldg(&cb4[t + NT * j]);
        keys[4 * j + 0] = fkey(v.x);
        keys[4 * j + 1] = fkey(v.y);
        keys[4 * j + 2] = fkey(v.z);
        keys[4 * j + 3] = fkey(v.w);
    }
    if (t < NV - NT * 6) {           // t < 384
        float4 v = __ldg(&cb4[t + NT * 6]);
        keys[24] = fkey(v.x); keys[25] = fkey(v.y);
        keys[26] = fkey(v.z); keys[27] = fkey(v.w);
    } else {
        keys[24] = keys[25] = keys[26] = keys[27] = 0u;
    }

    if (t == 0) s_ncand = 0;

    // ---------------- Phase 2: one-pass count at fixed threshold ----------------
    int c = 0;
#pragma unroll
    for (int j = 0; j < NK; j++)
        c += (keys[j] >= T1);
    unsigned int wsum = __reduce_add_sync(0xffffffffu, (unsigned int)c);
    if (lane == 0) s_wcnt[0][wid] = (int)wsum;
    __syncthreads();
    int tot = 0;
#pragma unroll
    for (int w = 0; w < 16; w++)
        tot += s_wcnt[0][w];

    unsigned int cut;
    if (tot >= TK && tot <= CAP) {
        cut = T1;                    // fast path (always taken for N(0,1) data)
    } else {
        // fallback: binary search for largest 11-bit prefix with count >= TK
        unsigned int T = 0;
#pragma unroll
        for (int bit = 10; bit >= 0; bit--) {
            unsigned int candT = T | (1u << bit);
            unsigned int Tsh = candT << 21;
            int cc = 0;
#pragma unroll
            for (int j = 0; j < NK; j++)
                cc += (keys[j] >= Tsh);
            unsigned int ws = __reduce_add_sync(0xffffffffu, (unsigned int)cc);
            int buf = bit & 1;
            if (lane == 0) s_wcnt[buf][wid] = (int)ws;
            __syncthreads();
            int tt = 0;
#pragma unroll
            for (int w = 0; w < 16; w++)
                tt += s_wcnt[buf][w];
            if (tt >= TK) T = candT;
            __syncthreads();
        }
        cut = T << 21;
        if (cut == 0) cut = 1;       // never collect zero-padded slots
    }

    // ---------------- Phase 3: collect candidates ----------------
#pragma unroll
    for (int j = 0; j < NK; j++) {
        if (keys[j] >= cut) {
            int idx = 4 * (t + NT * (j >> 2)) + (j & 3);
            if (idx < AN) {
                int pos = atomicAdd(&s_ncand, 1);
                if (pos < CAP)
                    s_cand[pos] = ((unsigned long long)keys[j] << 14) |
                                  (unsigned long long)(16383 - idx);
            }
        }
    }
    __syncthreads();

    // ---------------- Phase 4: exact ranking -> smem top-60 ----------------
    {
        int C = s_ncand;
        if (C > CAP) C = CAP;
        for (int cc2 = t; cc2 < C; cc2 += NT) {
            unsigned long long k = s_cand[cc2];
            int r = 0;
#pragma unroll 4
            for (int m = 0; m < C; m++)
                r += (s_cand[m] > k);
            if (r < TK) {
                int idx = 16383 - (int)(k & 16383ull);
                float logit = fkey_inv((unsigned int)(k >> 14));
                s_idx[r] = idx;
                s_sc[r]  = 1.0f / (1.0f + expf(-logit));
            }
        }
    }
    __syncthreads();

    // ---------------- Phase 5: parallel scattered gather (360 loads in flight) ----------------
    if (t < 6 * TK) {
        int comp = t / TK;           // 0..5 (uniform per chunk)
        int row  = t - comp * TK;
        int idx  = s_idx[row];
        size_t base = (size_t)b * 3 * AN;
        const float* src = (comp < 3) ? (off + base + (size_t)comp * AN)
                                      : (shp + base + (size_t)(comp - 3) * AN);
        s_gv[comp][row] = __ldg(&src[idx]);
    }
    __syncthreads();

    // ---------------- Phase 6: box build + valid ballot ----------------
    float sc = 0.0f, cz = 0, cy = 0, cx = 0, dz = 0, dy = 0, dx = 0;
    float l0 = 0, l1 = 0, l2 = 0, h0 = 0, h1 = 0, h2 = 0, vi = 0;
    if (t < TK) {
        int idx = s_idx[t];
        sc = s_sc[t];
        int z   = idx / 576;
        int rem = idx - z * 576;
        int y   = rem / 24;
        int x   = rem - y * 24;
        cz = ((float)z + s_gv[0][t]) * 4.0f;   // stride = 96/24 = 4
        cy = ((float)y + s_gv[1][t]) * 4.0f;
        cx = ((float)x + s_gv[2][t]) * 4.0f;
        dz = 2.0f * s_gv[3][t];
        dy = 2.0f * s_gv[4][t];
        dx = 2.0f * s_gv[5][t];
        l0 = cz - dz * 0.5f; l1 = cy - dy * 0.5f; l2 = cx - dx * 0.5f;
        h0 = cz + dz * 0.5f; h1 = cy + dy * 0.5f; h2 = cx + dx * 0.5f;
        vi = dz * dy * dx;
        s_l0[t] = l0; s_l1[t] = l1; s_l2[t] = l2;
        s_h0[t] = h0; s_h1[t] = h1; s_h2[t] = h2;
        s_vol[t] = vi;
    }
    {
        unsigned int vb = __ballot_sync(0xffffffffu, (t < TK) && (sc > 0.15f));
        if (wid < 2 && lane == 0) s_valid[wid] = vb;
    }
    __syncthreads();

    // ---------------- Phase 7: IoU threshold bitmask per row ----------------
    if (t < TK) {
        unsigned int mlo = 0, mhi = 0;
#pragma unroll 4
        for (int j = 0; j < TK; j++) {
            float iz = fminf(h0, s_h0[j]) - fmaxf(l0, s_l0[j]);
            float iy = fminf(h1, s_h1[j]) - fmaxf(l1, s_l1[j]);
            float ix = fminf(h2, s_h2[j]) - fmaxf(l2, s_l2[j]);
            float inter = fmaxf(iz, 0.0f) * fmaxf(iy, 0.0f) * fmaxf(ix, 0.0f);
            float uni = vi + s_vol[j] - inter;
            float iou = inter / fmaxf(uni, 1e-8f);
            unsigned int hit = (iou > 0.05f) && (j != t);
            if (j < 32) mlo |= hit << j;
            else        mhi |= hit << (j - 32);
        }
        s_mlo[t] = mlo;
        s_mhi[t] = mhi;
    }
    __syncthreads();

    // ---------------- Phase 8: serial bitmask NMS (one thread, register chain) ----------------
    if (t == 0) {
        unsigned long long valid = ((unsigned long long)s_valid[1] << 32) | s_valid[0];
        unsigned long long supp = 0, kept = 0;
        int r = 0;
#pragma unroll
        for (int i = 0; i < TK; i++) {
            unsigned long long mask_i =
                ((unsigned long long)s_mhi[i] << 32) | s_mlo[i];
            int v = (int)((valid >> i) & 1ull);
            int keep = v && (r < NMSK) && !((supp >> i) & 1ull);
            r += v;
            kept |= (unsigned long long)keep << i;
            if (keep) supp |= mask_i;
        }
        s_kept = kept;
    }
    __syncthreads();

    // ---------------- Phase 9: output (kept-first in index order, -1 padding) ----------------
    float* ob = out + (size_t)b * TK * 8;
    if (t < TK) {
        unsigned long long kept = s_kept;
        int nk = __popcll(kept);
        if ((kept >> t) & 1ull) {
            int pos = __popcll(kept & ((1ull << t) - 1ull));
            float4* o4 = (float4*)(ob + pos * 8);
            o4[0] = make_float4(1.0f, sc, cz, cy);
            o4[1] = make_float4(cx, dz, dy, dx);
        }
        if (t >= nk) {
            float4* o4 = (float4*)(ob + t * 8);
            o4[0] = make_float4(-1.0f, -1.0f, -1.0f, -1.0f);
            o4[1] = make_float4(-1.0f, -1.0f, -1.0f, -1.0f);
        }
    }
}

extern "C" void kernel_launch(void* const* d_in, const int* in_sizes, int n_in,
                              void* d_out, int out_size)
{
    const float* cls = (const float*)d_in[0];
    const float* shp = (const float*)d_in[1];
    const float* off = (const float*)d_in[2];
    float* out = (float*)d_out;
    detect_fused_kernel<<<NB, NT>>>(cls, shp, off, out);
}